// round 1
// baseline (speedup 1.0000x reference)
#include <cuda_runtime.h>
#include <math.h>

#define N_SPK 2048
#define M_UTT 16
#define D_DIM 128
#define ROWS  (N_SPK * M_UTT)   // 32768

#define BM 64
#define BN 64
#define BK 64
#define THREADS 256
#define NBLK (ROWS / BM)        // 512

// scratch (no cudaMalloc allowed)
__device__ float g_centroids[N_SPK * D_DIM];
__device__ float g_partial[NBLK];

// ---------------------------------------------------------------------------
// Kernel 1: centroids[n][d] = mean_m x[n][m][d]
// ---------------------------------------------------------------------------
__global__ __launch_bounds__(256) void centroid_kernel(const float* __restrict__ x) {
    int idx = blockIdx.x * 256 + threadIdx.x;     // over N_SPK * D_DIM (exact grid)
    int n = idx >> 7;
    int d = idx & 127;
    const float* p = x + (size_t)n * M_UTT * D_DIM + d;
    float s = 0.f;
#pragma unroll
    for (int m = 0; m < M_UTT; m++) s += p[m * D_DIM];
    g_centroids[idx] = s * (1.0f / M_UTT);
}

// ---------------------------------------------------------------------------
// Kernel 2: fused GEMM + online softmax denominator + target logit.
// Each block: 64 rows of x, loops over all 2048 centroids in chunks of 64.
// ---------------------------------------------------------------------------
__global__ __launch_bounds__(THREADS) void ge2e_main(const float* __restrict__ x,
                                                     const float* __restrict__ wp,
                                                     const float* __restrict__ bp) {
    // transposed smem tiles: As[k][row], pitch BM+1 to keep conflicts <= 2-way
    __shared__ float As[BK][BM + 1];
    __shared__ float Bs[BK][BN + 1];
    __shared__ float tgt_s[BM];
    __shared__ float red[BM][17];
    __shared__ float lossbuf[BM];

    const float w  = wp[0];
    const float bb = bp[0];

    const int tid = threadIdx.x;
    const int tx  = tid & 15;
    const int ty  = tid >> 4;
    const int tx4 = tx * 4;
    const int ty4 = ty * 4;
    const int rbase = blockIdx.x * BM;

    float sumexp[4] = {0.f, 0.f, 0.f, 0.f};
    int nrow[4];
#pragma unroll
    for (int i = 0; i < 4; i++) nrow[i] = (rbase + ty4 + i) >> 4;  // own speaker id

    for (int cbase = 0; cbase < N_SPK; cbase += BN) {
        float acc[4][4] = {};
        for (int k0 = 0; k0 < D_DIM; k0 += BK) {
            __syncthreads();
            // load A-slice (64 rows x 64 k) and B-slice, transposed into smem
#pragma unroll
            for (int it = 0; it < (BM * (BK / 4)) / THREADS; it++) {
                int t   = tid + it * THREADS;
                int row = t >> 4;              // 0..63
                int kq  = (t & 15) << 2;       // 0,4,...,60
                float4 v = *(const float4*)(x + (size_t)(rbase + row) * D_DIM + k0 + kq);
                As[kq + 0][row] = v.x; As[kq + 1][row] = v.y;
                As[kq + 2][row] = v.z; As[kq + 3][row] = v.w;
                float4 u = *(const float4*)(g_centroids + (size_t)(cbase + row) * D_DIM + k0 + kq);
                Bs[kq + 0][row] = u.x; Bs[kq + 1][row] = u.y;
                Bs[kq + 2][row] = u.z; Bs[kq + 3][row] = u.w;
            }
            __syncthreads();
#pragma unroll 16
            for (int k = 0; k < BK; k++) {
                float a0 = As[k][ty4 + 0], a1 = As[k][ty4 + 1];
                float a2 = As[k][ty4 + 2], a3 = As[k][ty4 + 3];
                float b0 = Bs[k][tx4 + 0], b1 = Bs[k][tx4 + 1];
                float b2 = Bs[k][tx4 + 2], b3 = Bs[k][tx4 + 3];
                acc[0][0] += a0 * b0; acc[0][1] += a0 * b1;
                acc[0][2] += a0 * b2; acc[0][3] += a0 * b3;
                acc[1][0] += a1 * b0; acc[1][1] += a1 * b1;
                acc[1][2] += a1 * b2; acc[1][3] += a1 * b3;
                acc[2][0] += a2 * b0; acc[2][1] += a2 * b1;
                acc[2][2] += a2 * b2; acc[2][3] += a2 * b3;
                acc[3][0] += a3 * b0; acc[3][1] += a3 * b1;
                acc[3][2] += a3 * b2; acc[3][3] += a3 * b3;
            }
        }
        // fold tile into per-row sum-of-exp; fix up the self-speaker column.
        // x rows are unit-norm => leave-one-out sim = (M*s - 1)/(M-1).
#pragma unroll
        for (int i = 0; i < 4; i++) {
#pragma unroll
            for (int j = 0; j < 4; j++) {
                int col = cbase + tx4 + j;
                float s = acc[i][j];
                float logit = fmaf(w, s, bb);
                if (col == nrow[i]) {
                    float dg = (M_UTT * s - 1.0f) * (1.0f / (M_UTT - 1));
                    logit = fmaf(w, dg, bb);
                    tgt_s[ty4 + i] = logit;      // exactly one writer per row
                }
                sumexp[i] += __expf(logit);      // logits bounded in [-17, 7]: no max needed
            }
        }
    }

    // per-row reduce of sumexp across the 16 tx-threads
#pragma unroll
    for (int i = 0; i < 4; i++) red[ty4 + i][tx] = sumexp[i];
    __syncthreads();
    if (tid < BM) {
        float S = 0.f;
#pragma unroll
        for (int t = 0; t < 16; t++) S += red[tid][t];
        lossbuf[tid] = logf(S) - tgt_s[tid];
    }
    __syncthreads();
    if (tid == 0) {
        float L = 0.f;
#pragma unroll
        for (int r = 0; r < BM; r++) L += lossbuf[r];
        g_partial[blockIdx.x] = L;
    }
}

// ---------------------------------------------------------------------------
// Kernel 3: deterministic final reduction -> mean loss scalar
// ---------------------------------------------------------------------------
__global__ __launch_bounds__(256) void reduce_kernel(float* __restrict__ out) {
    __shared__ float s[256];
    float v = g_partial[threadIdx.x] + g_partial[threadIdx.x + 256];
    s[threadIdx.x] = v;
    __syncthreads();
    for (int o = 128; o > 0; o >>= 1) {
        if (threadIdx.x < o) s[threadIdx.x] += s[threadIdx.x + o];
        __syncthreads();
    }
    if (threadIdx.x == 0) out[0] = s[0] * (1.0f / (float)ROWS);
}

extern "C" void kernel_launch(void* const* d_in, const int* in_sizes, int n_in,
                              void* d_out, int out_size) {
    const float* x = (const float*)d_in[0];
    const float* w = (const float*)d_in[1];
    const float* b = (const float*)d_in[2];
    float* out = (float*)d_out;

    centroid_kernel<<<(N_SPK * D_DIM) / 256, 256>>>(x);
    ge2e_main<<<NBLK, THREADS>>>(x, w, b);
    reduce_kernel<<<1, 256>>>(out);
}

// round 3
// speedup vs baseline: 5.6133x; 5.6133x over previous
#include <cuda_runtime.h>
#include <cstdint>
#include <math.h>

#define N_SPK 2048
#define M_UTT 16
#define D_DIM 128
#define ROWS  32768

#define BM 256                 // rows per CTA
#define BN 128                 // centroid cols per chunk
#define NCTA (ROWS / BM)       // 128
#define NCHUNK (N_SPK / BN)    // 16
#define THREADS 256

#define A_F4 (16 * 16 * 32)    // per-CTA packed A float4 count = 8192 (128KB)
#define STAGE_F4 2048          // 32KB per B half-chunk stage
#define DYN_SMEM (A_F4 * 16 + 2 * STAGE_F4 * 16)   // 196608

// packed tf32 operands (fragment-order) — __device__ scratch, no cudaMalloc
__device__ float4 gA[NCTA * A_F4];                   // 16MB
__device__ float4 gB[(N_SPK / 16) * 16 * 32];        // 1MB: [npair128][kstep16][lane32]
__device__ float  g_partial[NCTA];

// ---------------------------------------------------------------------------
__device__ __forceinline__ uint32_t smem_u32(const void* p) {
    uint32_t a;
    asm("{ .reg .u64 t; cvta.to.shared.u64 t, %1; cvt.u32.u64 %0, t; }" : "=r"(a) : "l"(p));
    return a;
}
__device__ __forceinline__ void cp_async16(uint32_t dst, const void* src) {
    asm volatile("cp.async.cg.shared.global [%0], [%1], 16;" :: "r"(dst), "l"(src));
}
#define CP_COMMIT() asm volatile("cp.async.commit_group;" ::: "memory")
#define CP_WAIT0()  asm volatile("cp.async.wait_group 0;" ::: "memory")
#define CP_WAIT1()  asm volatile("cp.async.wait_group 1;" ::: "memory")

__device__ __forceinline__ float tf32r(float x) {     // round-to-nearest tf32
    float o;
    asm("cvt.rna.tf32.f32 %0, %1;" : "=f"(o) : "f"(x));
    return o;
}

// d += a * b  (m16n8k8 tf32, row.col)
#define MMA(d, a, b0, b1) \
    asm volatile("mma.sync.aligned.m16n8k8.row.col.f32.tf32.tf32.f32 " \
                 "{%0,%1,%2,%3},{%4,%5,%6,%7},{%8,%9},{%0,%1,%2,%3};" \
                 : "+f"((d)[0]), "+f"((d)[1]), "+f"((d)[2]), "+f"((d)[3]) \
                 : "r"((a).x), "r"((a).y), "r"((a).z), "r"((a).w), "r"(b0), "r"(b1))

// ---------------------------------------------------------------------------
// Pre-kernel 1: centroids -> gB in fragment order (tf32-rounded)
//   element (n,d): nt=n>>3, g=n&7, kstep=d>>3, t4=d&3, half=(d&7)>>2
//   gB[nt>>1][kstep][g*4+t4].comp[(nt&1)*2+half]
// ---------------------------------------------------------------------------
__global__ __launch_bounds__(256) void centroid_pack_kernel(const float* __restrict__ x) {
    int idx = blockIdx.x * 256 + threadIdx.x;   // over N_SPK * 32
    int n  = idx >> 5;
    int dq = idx & 31;
    const float4* p = reinterpret_cast<const float4*>(x) + (size_t)n * M_UTT * 32 + dq;
    float4 s = make_float4(0.f, 0.f, 0.f, 0.f);
#pragma unroll
    for (int m = 0; m < M_UTT; m++) {
        float4 v = p[m * 32];
        s.x += v.x; s.y += v.y; s.z += v.z; s.w += v.w;
    }
    const float inv = 1.0f / M_UTT;
    float c[4] = { s.x * inv, s.y * inv, s.z * inv, s.w * inv };
    int nt = n >> 3, g = n & 7;
    float* out = reinterpret_cast<float*>(gB);
#pragma unroll
    for (int j = 0; j < 4; j++) {
        int d = dq * 4 + j;
        int kstep = d >> 3, r = d & 7;
        int t4 = r & 3, half = r >> 2;
        int comp = (nt & 1) * 2 + half;
        size_t f4 = (size_t)(((nt >> 1) * 16 + kstep) * 32 + g * 4 + t4);
        out[f4 * 4 + comp] = tf32r(c[j]);
    }
}

// ---------------------------------------------------------------------------
// Pre-kernel 2: pack x -> gA fragment order (tf32-rounded)
//   gA[cta][mtile][kstep][lane] = (A[r][k], A[r+8][k], A[r][k+4], A[r+8][k+4])
// ---------------------------------------------------------------------------
__global__ __launch_bounds__(256) void pack_a_kernel(const float* __restrict__ x) {
    int id = blockIdx.x * 256 + threadIdx.x;    // over NCTA*16*16*32 = 1048576
    int lane  = id & 31;
    int kstep = (id >> 5) & 15;
    int mtile = (id >> 9) & 15;
    int cta   = id >> 13;
    int g = lane >> 2, t4 = lane & 3;
    int r = cta * BM + mtile * 16 + g;
    int k = kstep * 8 + t4;
    const float* xr = x + (size_t)r * D_DIM;
    float4 o;
    o.x = tf32r(xr[k]);
    o.y = tf32r(xr[8 * D_DIM + k]);
    o.z = tf32r(xr[k + 4]);
    o.w = tf32r(xr[8 * D_DIM + k + 4]);
    gA[id] = o;
}

// ---------------------------------------------------------------------------
// stage loader: half-chunk t (chunk c=t>>1, half h=t&1) of B, 32KB contiguous-ish
// ---------------------------------------------------------------------------
__device__ __forceinline__ void load_stage(uint32_t dst, int t, int tid) {
    int c = t >> 1, h = t & 1;
    const float4* src = gB + (size_t)(8 * c) * 512 + h * 256;
#pragma unroll
    for (int i = 0; i < 8; i++) {
        int f = tid + i * 256;
        int p = f >> 8, off = f & 255;
        cp_async16(dst + f * 16, src + (size_t)p * 512 + off);
    }
}

// ---------------------------------------------------------------------------
// Main kernel: tf32 mma.sync GEMM fused with softmax-denominator reduction
// 8 warps as 4(m) x 2(n), warp tile 64x64, BM=256, BN=128
// ---------------------------------------------------------------------------
__global__ __launch_bounds__(THREADS, 1) void ge2e_main(const float* __restrict__ wp,
                                                        const float* __restrict__ bp) {
    extern __shared__ float4 dsm[];
    __shared__ float s_tgt[BM];
    __shared__ float s_red[BM][2];
    __shared__ float s_loss[BM];

    const int tid  = threadIdx.x;
    const int wid  = tid >> 5;
    const int lane = tid & 31;
    const int wm = wid >> 1;            // 0..3
    const int wn = wid & 1;             // 0..1
    const int g  = lane >> 2;
    const int t4 = lane & 3;

    const float w  = wp[0];
    const float bb = bp[0];

    const uint32_t smA  = smem_u32(dsm);
    const uint32_t smB0 = smA + A_F4 * 16;
    const uint32_t smB1 = smB0 + STAGE_F4 * 16;

    // prologue: A (resident) + B stage0 in group0, B stage1 in group1
    const float4* gAs = gA + (size_t)blockIdx.x * A_F4;
#pragma unroll
    for (int i = 0; i < 32; i++)
        cp_async16(smA + (tid + i * 256) * 16, gAs + tid + i * 256);
    load_stage(smB0, 0, tid);
    CP_COMMIT();
    load_stage(smB1, 1, tid);
    CP_COMMIT();

    float acc[4][8][4];
#pragma unroll
    for (int mt = 0; mt < 4; mt++)
#pragma unroll
        for (int nt = 0; nt < 8; nt++)
#pragma unroll
            for (int q = 0; q < 4; q++) acc[mt][nt][q] = 0.f;

    float rsum[4][2] = {};
    int lrow[4], sp0[4], sp1[4];
#pragma unroll
    for (int mt = 0; mt < 4; mt++) {
        lrow[mt] = wm * 64 + mt * 16 + g;
        int gr = blockIdx.x * BM + lrow[mt];
        sp0[mt] = gr >> 4;
        sp1[mt] = (gr + 8) >> 4;
    }

    const uint4* As4 = reinterpret_cast<const uint4*>(dsm);

    for (int t = 0; t < 2 * NCHUNK; t++) {
        if (t == 2 * NCHUNK - 1) CP_WAIT0(); else CP_WAIT1();
        __syncthreads();

        const int h = t & 1;
        const uint4* Bst = reinterpret_cast<const uint4*>(dsm + A_F4 + h * STAGE_F4);

#pragma unroll
        for (int s = 0; s < 8; s++) {
            const int ks = h * 8 + s;
            uint4 a[4], bq[4];
#pragma unroll
            for (int mt = 0; mt < 4; mt++)
                a[mt] = As4[((wm * 4 + mt) * 16 + ks) * 32 + lane];
#pragma unroll
            for (int p = 0; p < 4; p++)
                bq[p] = Bst[((wn * 4 + p) * 8 + s) * 32 + lane];
#pragma unroll
            for (int mt = 0; mt < 4; mt++)
#pragma unroll
                for (int p = 0; p < 4; p++) {
                    MMA(acc[mt][2 * p],     a[mt], bq[p].x, bq[p].y);
                    MMA(acc[mt][2 * p + 1], a[mt], bq[p].z, bq[p].w);
                }
        }
        __syncthreads();
        if (t + 2 < 2 * NCHUNK) {
            load_stage(smB0 + (t & 1) * (STAGE_F4 * 16), t + 2, tid);
            CP_COMMIT();
        }

        if (h) {    // chunk c complete: fold into per-row sum-of-exp
            const int c = t >> 1;
            const int cb = c * BN + wn * 64;
#pragma unroll
            for (int mt = 0; mt < 4; mt++) {
#pragma unroll
                for (int nt = 0; nt < 8; nt++) {
                    const int col = cb + nt * 8 + t4 * 2;
                    float* A4 = acc[mt][nt];
                    // c0: row g, col; c1: row g, col+1; c2: row g+8, col; c3: row g+8, col+1
                    {
                        float v = A4[0]; float l = fmaf(w, v, bb);
                        if (col == sp0[mt]) {
                            l = fmaf(w, fmaf(v, 16.f, -1.f) * (1.f / 15.f), bb);
                            s_tgt[lrow[mt]] = l;
                        }
                        rsum[mt][0] += __expf(l);
                    }
                    {
                        float v = A4[1]; float l = fmaf(w, v, bb);
                        if (col + 1 == sp0[mt]) {
                            l = fmaf(w, fmaf(v, 16.f, -1.f) * (1.f / 15.f), bb);
                            s_tgt[lrow[mt]] = l;
                        }
                        rsum[mt][0] += __expf(l);
                    }
                    {
                        float v = A4[2]; float l = fmaf(w, v, bb);
                        if (col == sp1[mt]) {
                            l = fmaf(w, fmaf(v, 16.f, -1.f) * (1.f / 15.f), bb);
                            s_tgt[lrow[mt] + 8] = l;
                        }
                        rsum[mt][1] += __expf(l);
                    }
                    {
                        float v = A4[3]; float l = fmaf(w, v, bb);
                        if (col + 1 == sp1[mt]) {
                            l = fmaf(w, fmaf(v, 16.f, -1.f) * (1.f / 15.f), bb);
                            s_tgt[lrow[mt] + 8] = l;
                        }
                        rsum[mt][1] += __expf(l);
                    }
                    A4[0] = 0.f; A4[1] = 0.f; A4[2] = 0.f; A4[3] = 0.f;
                }
            }
        }
    }

    // reduce across the 4 t4-lanes sharing each row, then across the 2 n-warps
#pragma unroll
    for (int mt = 0; mt < 4; mt++)
#pragma unroll
        for (int hh = 0; hh < 2; hh++) {
            float v = rsum[mt][hh];
            v += __shfl_xor_sync(0xFFFFFFFFu, v, 1);
            v += __shfl_xor_sync(0xFFFFFFFFu, v, 2);
            if (t4 == 0) s_red[lrow[mt] + hh * 8][wn] = v;
        }
    __syncthreads();
    if (tid < BM) {
        float S = s_red[tid][0] + s_red[tid][1];
        s_loss[tid] = logf(S) - s_tgt[tid];
    }
    __syncthreads();
    if (tid == 0) {
        float L = 0.f;
#pragma unroll 8
        for (int r = 0; r < BM; r++) L += s_loss[r];
        g_partial[blockIdx.x] = L;
    }
}

// ---------------------------------------------------------------------------
// final reduction -> mean loss
// ---------------------------------------------------------------------------
__global__ __launch_bounds__(128) void reduce_kernel(float* __restrict__ out) {
    __shared__ float s[128];
    s[threadIdx.x] = g_partial[threadIdx.x];
    __syncthreads();
    for (int o = 64; o > 0; o >>= 1) {
        if (threadIdx.x < o) s[threadIdx.x] += s[threadIdx.x + o];
        __syncthreads();
    }
    if (threadIdx.x == 0) out[0] = s[0] * (1.0f / (float)ROWS);
}

extern "C" void kernel_launch(void* const* d_in, const int* in_sizes, int n_in,
                              void* d_out, int out_size) {
    const float* x = (const float*)d_in[0];
    const float* w = (const float*)d_in[1];
    const float* b = (const float*)d_in[2];
    float* out = (float*)d_out;

    cudaFuncSetAttribute(ge2e_main, cudaFuncAttributeMaxDynamicSharedMemorySize, DYN_SMEM);

    centroid_pack_kernel<<<(N_SPK * 32) / 256, 256>>>(x);
    pack_a_kernel<<<(NCTA * A_F4) / 256, 256>>>(x);
    ge2e_main<<<NCTA, THREADS, DYN_SMEM>>>(w, b);
    reduce_kernel<<<1, 128>>>(out);
}

// round 4
// speedup vs baseline: 8.3179x; 1.4818x over previous
#include <cuda_runtime.h>
#include <cuda_fp16.h>
#include <cstdint>
#include <math.h>

#define N_SPK 2048
#define M_UTT 16
#define D_DIM 128
#define ROWS  32768

#define BM 256                  // rows per CTA
#define BN 128                  // centroid cols per chunk
#define NCTA (ROWS / BM)        // 128
#define NCHUNK (N_SPK / BN)     // 16
#define THREADS 256

#define A_U4 (16 * 8 * 32)      // per-CTA packed A uint4 count = 4096 (64KB)
#define STAGE_U4 2048           // 32KB per B chunk stage
#define DYN_SMEM (A_U4 * 16 + 2 * STAGE_U4 * 16)   // 131072

// packed fp16 operands in fragment order (__device__ scratch; no cudaMalloc)
__device__ uint4 gAh[NCTA * A_U4];               // 8MB
__device__ uint4 gBh[NCHUNK * STAGE_U4];         // 512KB
__device__ float gC[N_SPK * D_DIM];              // centroids fp32, 1MB
__device__ float g_partial[NCTA];
__device__ unsigned g_ctr = 0;

// ---------------------------------------------------------------------------
__device__ __forceinline__ uint32_t smem_u32(const void* p) {
    uint32_t a;
    asm("{ .reg .u64 t; cvta.to.shared.u64 t, %1; cvt.u32.u64 %0, t; }" : "=r"(a) : "l"(p));
    return a;
}
__device__ __forceinline__ void cp_async16(uint32_t dst, const void* src) {
    asm volatile("cp.async.cg.shared.global [%0], [%1], 16;" :: "r"(dst), "l"(src));
}
#define CP_COMMIT() asm volatile("cp.async.commit_group;" ::: "memory")
#define CP_WAIT0()  asm volatile("cp.async.wait_group 0;" ::: "memory")
#define CP_WAIT1()  asm volatile("cp.async.wait_group 1;" ::: "memory")

__device__ __forceinline__ uint32_t pack2(float lo, float hi) {
    __half2 h = __floats2half2_rn(lo, hi);
    return *reinterpret_cast<uint32_t*>(&h);
}
__device__ __forceinline__ float ex2(float x) {
    float y;
    asm("ex2.approx.f32 %0, %1;" : "=f"(y) : "f"(x));
    return y;
}

// d += a * b  (m16n8k16 f16 -> f32)
#define MMA(d, a, b0, b1) \
    asm volatile("mma.sync.aligned.m16n8k16.row.col.f32.f16.f16.f32 " \
                 "{%0,%1,%2,%3},{%4,%5,%6,%7},{%8,%9},{%0,%1,%2,%3};" \
                 : "+f"((d)[0]), "+f"((d)[1]), "+f"((d)[2]), "+f"((d)[3]) \
                 : "r"((a).x), "r"((a).y), "r"((a).z), "r"((a).w), "r"(b0), "r"(b1))

// ---------------------------------------------------------------------------
// Pre-kernel 1: centroids (fp32, coalesced)
// ---------------------------------------------------------------------------
__global__ __launch_bounds__(256) void centroid_kernel(const float* __restrict__ x) {
    int idx = blockIdx.x * 256 + threadIdx.x;       // over N_SPK*32
    int n = idx >> 5;
    int d4 = idx & 31;
    const float4* p = reinterpret_cast<const float4*>(x) + (size_t)n * M_UTT * 32 + d4;
    float4 s = make_float4(0.f, 0.f, 0.f, 0.f);
#pragma unroll
    for (int m = 0; m < M_UTT; m++) {
        float4 v = p[m * 32];
        s.x += v.x; s.y += v.y; s.z += v.z; s.w += v.w;
    }
    const float inv = 1.0f / M_UTT;
    s.x *= inv; s.y *= inv; s.z *= inv; s.w *= inv;
    reinterpret_cast<float4*>(gC)[idx] = s;
}

// ---------------------------------------------------------------------------
// Pre-kernel 2: pack x -> A fragments (fp16).  id = [cta7][mt4][ks3][lane5]
// frag uint4 = { {A[r][k0],A[r][k0+1]}, {A[r+8][k0..]}, {A[r][k0+8..]}, {A[r+8][k0+8..]} }
// ---------------------------------------------------------------------------
__global__ __launch_bounds__(256) void pack_a_kernel(const float* __restrict__ x) {
    int id = blockIdx.x * 256 + threadIdx.x;        // 0..524287
    int lane = id & 31, ks = (id >> 5) & 7, mt = (id >> 8) & 15, cta = id >> 12;
    int g = lane >> 2, t = lane & 3;
    int r0 = cta * BM + mt * 16 + g;
    int k0 = ks * 16 + t * 2;
    const float* p0 = x + (size_t)r0 * D_DIM;
    const float* p1 = p0 + 8 * D_DIM;
    float2 alo = *(const float2*)(p0 + k0);
    float2 blo = *(const float2*)(p1 + k0);
    float2 ahi = *(const float2*)(p0 + k0 + 8);
    float2 bhi = *(const float2*)(p1 + k0 + 8);
    uint4 o;
    o.x = pack2(alo.x, alo.y);
    o.y = pack2(blo.x, blo.y);
    o.z = pack2(ahi.x, ahi.y);
    o.w = pack2(bhi.x, bhi.y);
    gAh[id] = o;
}

// ---------------------------------------------------------------------------
// Pre-kernel 3: pack centroids -> B fragments.  id = [c4][ks3][pp3][lane5]
// uint4 = { even-ntile b0,b1, odd-ntile b0,b1 }
// ---------------------------------------------------------------------------
__global__ __launch_bounds__(256) void pack_b_kernel() {
    int id = blockIdx.x * 256 + threadIdx.x;        // 0..32767
    int lane = id & 31, pp = (id >> 5) & 7, ks = (id >> 8) & 7, c = id >> 11;
    int g = lane >> 2, t = lane & 3;
    int col0 = c * BN + pp * 16 + g;
    int k0 = ks * 16 + t * 2;
    const float* C0 = gC + (size_t)col0 * D_DIM;
    const float* C1 = C0 + 8 * D_DIM;
    uint4 o;
    o.x = pack2(C0[k0],     C0[k0 + 1]);
    o.y = pack2(C0[k0 + 8], C0[k0 + 9]);
    o.z = pack2(C1[k0],     C1[k0 + 1]);
    o.w = pack2(C1[k0 + 8], C1[k0 + 9]);
    gBh[id] = o;
}

// ---------------------------------------------------------------------------
__device__ __forceinline__ void load_stage(uint32_t dst, int c, int tid) {
    const uint4* src = gBh + (size_t)c * STAGE_U4;
#pragma unroll
    for (int i = 0; i < 8; i++) {
        int f = tid + i * 256;
        cp_async16(dst + f * 16, src + f);
    }
}

// ---------------------------------------------------------------------------
// Main: fp16 mma.sync GEMM fused with log2-domain softmax reduction.
// 8 warps as 4(m) x 2(n); warp tile 64x64; final reduce folded in (last CTA).
// ---------------------------------------------------------------------------
__global__ __launch_bounds__(THREADS, 1) void ge2e_main(const float* __restrict__ wp,
                                                        const float* __restrict__ bp,
                                                        float* __restrict__ out) {
    extern __shared__ uint4 dsm[];
    __shared__ float s_tgt[BM];          // log2-domain target logit
    __shared__ float s_red[BM][2];
    __shared__ float s_loss[BM];
    __shared__ bool  s_last;

    const int tid  = threadIdx.x;
    const int wid  = tid >> 5;
    const int lane = tid & 31;
    const int wm = wid >> 1;
    const int wn = wid & 1;
    const int g  = lane >> 2;
    const int t4 = lane & 3;

    const float L2E = 1.44269504088896341f;
    const float w2  = wp[0] * L2E;            // log2-domain scale
    const float b2  = bp[0] * L2E;
    const float wd  = w2 * (16.0f / 15.0f);   // diag fixup: slope
    const float bd  = b2 - w2 * (1.0f / 15.0f);

    const uint32_t smA  = smem_u32(dsm);
    const uint32_t smB0 = smA + A_U4 * 16;

    // prologue: A resident + stage0 (group0), stage1 (group1)
    const uint4* gAs = gAh + (size_t)blockIdx.x * A_U4;
#pragma unroll
    for (int i = 0; i < 16; i++)
        cp_async16(smA + (tid + i * 256) * 16, gAs + tid + i * 256);
    load_stage(smB0, 0, tid);
    CP_COMMIT();
    load_stage(smB0 + STAGE_U4 * 16, 1, tid);
    CP_COMMIT();

    float acc[4][8][4];
#pragma unroll
    for (int mt = 0; mt < 4; mt++)
#pragma unroll
        for (int nt = 0; nt < 8; nt++)
#pragma unroll
            for (int q = 0; q < 4; q++) acc[mt][nt][q] = 0.f;

    float rsum[4][2] = {};
    int lrow[4], sp0[4], sp1[4];
#pragma unroll
    for (int mt = 0; mt < 4; mt++) {
        lrow[mt] = wm * 64 + mt * 16 + g;
        int gr = blockIdx.x * BM + lrow[mt];
        sp0[mt] = gr >> 4;
        sp1[mt] = (gr + 8) >> 4;
    }

    for (int c = 0; c < NCHUNK; c++) {
        if (c == NCHUNK - 1) CP_WAIT0(); else CP_WAIT1();
        __syncthreads();

        const uint4* Bst = dsm + A_U4 + (c & 1) * STAGE_U4;
#pragma unroll
        for (int s = 0; s < 8; s++) {
            uint4 a[4], bq[4];
#pragma unroll
            for (int mt = 0; mt < 4; mt++)
                a[mt] = dsm[((wm * 4 + mt) * 8 + s) * 32 + lane];
#pragma unroll
            for (int p = 0; p < 4; p++)
                bq[p] = Bst[(s * 8 + wn * 4 + p) * 32 + lane];
#pragma unroll
            for (int mt = 0; mt < 4; mt++)
#pragma unroll
                for (int p = 0; p < 4; p++) {
                    MMA(acc[mt][2 * p],     a[mt], bq[p].x, bq[p].y);
                    MMA(acc[mt][2 * p + 1], a[mt], bq[p].z, bq[p].w);
                }
        }
        __syncthreads();
        if (c + 2 < NCHUNK) {
            load_stage(smB0 + (c & 1) * (STAGE_U4 * 16), c + 2, tid);
            CP_COMMIT();
        }

        // fold chunk into per-row sum of 2^l2 (== sum of exp(logit))
        const int cb = c * BN + wn * 64;
#pragma unroll
        for (int mt = 0; mt < 4; mt++) {
#pragma unroll
            for (int nt = 0; nt < 8; nt++) {
                const int col = cb + nt * 8 + t4 * 2;
                float* A4 = acc[mt][nt];
                {
                    float v = A4[0]; float l = fmaf(w2, v, b2);
                    if (col == sp0[mt]) { l = fmaf(wd, v, bd); s_tgt[lrow[mt]] = l; }
                    rsum[mt][0] += ex2(l);
                }
                {
                    float v = A4[1]; float l = fmaf(w2, v, b2);
                    if (col + 1 == sp0[mt]) { l = fmaf(wd, v, bd); s_tgt[lrow[mt]] = l; }
                    rsum[mt][0] += ex2(l);
                }
                {
                    float v = A4[2]; float l = fmaf(w2, v, b2);
                    if (col == sp1[mt]) { l = fmaf(wd, v, bd); s_tgt[lrow[mt] + 8] = l; }
                    rsum[mt][1] += ex2(l);
                }
                {
                    float v = A4[3]; float l = fmaf(w2, v, b2);
                    if (col + 1 == sp1[mt]) { l = fmaf(wd, v, bd); s_tgt[lrow[mt] + 8] = l; }
                    rsum[mt][1] += ex2(l);
                }
                A4[0] = 0.f; A4[1] = 0.f; A4[2] = 0.f; A4[3] = 0.f;
            }
        }
    }

    // reduce 4 t4-lanes per row, then the 2 n-warps
#pragma unroll
    for (int mt = 0; mt < 4; mt++)
#pragma unroll
        for (int hh = 0; hh < 2; hh++) {
            float v = rsum[mt][hh];
            v += __shfl_xor_sync(0xFFFFFFFFu, v, 1);
            v += __shfl_xor_sync(0xFFFFFFFFu, v, 2);
            if (t4 == 0) s_red[lrow[mt] + hh * 8][wn] = v;
        }
    __syncthreads();
    if (tid < BM) {
        float S = s_red[tid][0] + s_red[tid][1];
        // loss_row = ln(sumexp) - target = ln2 * (log2(S) - t2)
        s_loss[tid] = (log2f(S) - s_tgt[tid]) * 0.69314718055994531f;
    }
    __syncthreads();
    if (tid == 0) {
        float L = 0.f;
#pragma unroll 8
        for (int r = 0; r < BM; r++) L += s_loss[r];
        g_partial[blockIdx.x] = L;
        __threadfence();
        unsigned old = atomicAdd(&g_ctr, 1u);
        s_last = (old == NCTA - 1);
    }
    __syncthreads();

    if (s_last) {                        // last CTA: final deterministic reduce
        if (tid == 0) g_ctr = 0;
        __threadfence();
        if (tid < NCTA) s_loss[tid] = g_partial[tid];
        __syncthreads();
        for (int o = NCTA / 2; o > 0; o >>= 1) {
            if (tid < o) s_loss[tid] += s_loss[tid + o];
            __syncthreads();
        }
        if (tid == 0) out[0] = s_loss[0] * (1.0f / (float)ROWS);
    }
}

extern "C" void kernel_launch(void* const* d_in, const int* in_sizes, int n_in,
                              void* d_out, int out_size) {
    const float* x = (const float*)d_in[0];
    const float* w = (const float*)d_in[1];
    const float* b = (const float*)d_in[2];
    float* out = (float*)d_out;

    cudaFuncSetAttribute(ge2e_main, cudaFuncAttributeMaxDynamicSharedMemorySize, DYN_SMEM);

    centroid_kernel<<<(N_SPK * 32) / 256, 256>>>(x);
    pack_a_kernel<<<(NCTA * A_U4) / 256, 256>>>(x);
    pack_b_kernel<<<(NCHUNK * STAGE_U4) / 256, 256>>>();
    ge2e_main<<<NCTA, THREADS, DYN_SMEM>>>(w, b, out);
}